// round 1
// baseline (speedup 1.0000x reference)
#include <cuda_runtime.h>

#define BB 2
#define CC 1024
#define TT 2048
#define HH 16
#define DH 64
#define LN_EPS 1e-6f

// Scratch (no allocations allowed -> device globals)
__device__ float g_qkv[(size_t)BB * 3 * CC * TT];   // [b][3C][T]
__device__ float g_ctx[(size_t)BB * CC * TT];       // [b][C][T]
__device__ float g_y[(size_t)BB * CC * TT];         // pre-LN
// ---------------------------------------------------------------------------
// SGEMM: C[M,N] = A[M,K] @ B[K,N] (+ residual), batched over blockIdx.z on B/C/R
// 128x128x8 tile, 256 threads, 8x8 per-thread register tile.
// ---------------------------------------------------------------------------
template <bool RES>
__global__ void __launch_bounds__(256) sgemm_kernel(
    const float* __restrict__ A, const float* __restrict__ Bmat,
    const float* __restrict__ Res, float* __restrict__ Cmat,
    int M, int N, int K, long strideB, long strideC, long strideR)
{
    __shared__ float As[8][128];
    __shared__ float Bs[8][128];

    const int tid = threadIdx.x;
    const int tx = tid & 15;        // 0..15 -> 8 output cols each
    const int ty = tid >> 4;        // 0..15 -> 8 output rows each

    const float* Bb = Bmat + (long)blockIdx.z * strideB;
    float* Cb = Cmat + (long)blockIdx.z * strideC;
    const float* Rb = RES ? (Res + (long)blockIdx.z * strideR) : nullptr;

    const int row0 = blockIdx.y * 128;
    const int col0 = blockIdx.x * 128;

    const int arow = tid >> 1;          // 0..127
    const int acol = (tid & 1) * 4;     // 0 or 4
    const int brow = tid >> 5;          // 0..7
    const int bcol = (tid & 31) * 4;    // 0..124

    const float* Ap = A + (long)(row0 + arow) * K + acol;
    const float* Bp = Bb + (long)brow * N + col0 + bcol;

    float acc[8][8];
#pragma unroll
    for (int i = 0; i < 8; i++)
#pragma unroll
        for (int j = 0; j < 8; j++) acc[i][j] = 0.0f;

    for (int kb = 0; kb < K; kb += 8) {
        const float4 a = *(const float4*)(Ap + kb);
        const float4 bv = *(const float4*)(Bp + (long)kb * N);
        __syncthreads();
        As[acol + 0][arow] = a.x;
        As[acol + 1][arow] = a.y;
        As[acol + 2][arow] = a.z;
        As[acol + 3][arow] = a.w;
        *(float4*)&Bs[brow][bcol] = bv;
        __syncthreads();
#pragma unroll
        for (int kk = 0; kk < 8; kk++) {
            float av[8], bw[8];
            *(float4*)&av[0] = *(float4*)&As[kk][ty * 8];
            *(float4*)&av[4] = *(float4*)&As[kk][ty * 8 + 4];
            *(float4*)&bw[0] = *(float4*)&Bs[kk][tx * 8];
            *(float4*)&bw[4] = *(float4*)&Bs[kk][tx * 8 + 4];
#pragma unroll
            for (int i = 0; i < 8; i++)
#pragma unroll
                for (int j = 0; j < 8; j++) acc[i][j] = fmaf(av[i], bw[j], acc[i][j]);
        }
    }

#pragma unroll
    for (int i = 0; i < 8; i++) {
        const int gr = row0 + ty * 8 + i;
        float* crow = Cb + (long)gr * N + col0 + tx * 8;
#pragma unroll
        for (int j0 = 0; j0 < 8; j0 += 4) {
            float4 r = make_float4(acc[i][j0], acc[i][j0 + 1], acc[i][j0 + 2], acc[i][j0 + 3]);
            if (RES) {
                const float4 rr = *(const float4*)(Rb + (long)gr * N + col0 + tx * 8 + j0);
                r.x += rr.x; r.y += rr.y; r.z += rr.z; r.w += rr.w;
            }
            *(float4*)(crow + j0) = r;
        }
    }
}

// ---------------------------------------------------------------------------
// Flash-style attention. Block = (b, h, 64-query tile). 256 threads (16x16).
// Thread (tx,ty): q rows ty*4..+3, k cols / d cols tx*4..+3.
// Smem: Qs[64][64], Ks[64][64], Pts[64][68] (P transposed [k][q]), Vs[64][65].
// ---------------------------------------------------------------------------
#define SM_QS 0
#define SM_KS (64 * 64)
#define SM_PT (2 * 64 * 64)
#define SM_VS (2 * 64 * 64 + 64 * 68)
#define ATTN_SMEM ((2 * 64 * 64 + 64 * 68 + 64 * 65) * 4)

__global__ void __launch_bounds__(256) attn_kernel()
{
    extern __shared__ float sm[];
    float* Qs = sm + SM_QS;
    float* Ks = sm + SM_KS;
    float* Pts = sm + SM_PT;   // pitch 68
    float* Vs = sm + SM_VS;    // pitch 65

    const int tid = threadIdx.x;
    const int tx = tid & 15;
    const int ty = tid >> 4;
    const int b = blockIdx.z, h = blockIdx.y;
    const int q0 = blockIdx.x * 64;

    const float* Qg = g_qkv + ((long)b * 3 * CC + h * DH) * TT;
    const float* Kg = Qg + (long)CC * TT;
    const float* Vg = Qg + 2L * CC * TT;

    // load Q tile: rows d(64) x cols q(64)
    for (int i = tid; i < 64 * 16; i += 256) {
        const int r = i >> 4, c4 = (i & 15) << 2;
        *(float4*)&Qs[r * 64 + c4] = *(const float4*)&Qg[(long)r * TT + q0 + c4];
    }

    float m_i[4], l_i[4], Oacc[4][4];
#pragma unroll
    for (int i = 0; i < 4; i++) {
        m_i[i] = -__int_as_float(0x7f800000);  // -inf
        l_i[i] = 0.0f;
#pragma unroll
        for (int j = 0; j < 4; j++) Oacc[i][j] = 0.0f;
    }
    __syncthreads();

    for (int k0 = 0; k0 < TT; k0 += 64) {
        // load K (natural) and V (pitch 65)
        for (int i = tid; i < 64 * 16; i += 256) {
            const int r = i >> 4, c4 = (i & 15) << 2;
            *(float4*)&Ks[r * 64 + c4] = *(const float4*)&Kg[(long)r * TT + k0 + c4];
            const float4 v = *(const float4*)&Vg[(long)r * TT + k0 + c4];
            Vs[r * 65 + c4 + 0] = v.x;
            Vs[r * 65 + c4 + 1] = v.y;
            Vs[r * 65 + c4 + 2] = v.z;
            Vs[r * 65 + c4 + 3] = v.w;
        }
        __syncthreads();

        // S = Q^T K  (4x4 per thread)
        float S[4][4];
#pragma unroll
        for (int i = 0; i < 4; i++)
#pragma unroll
            for (int j = 0; j < 4; j++) S[i][j] = 0.0f;
#pragma unroll 8
        for (int d = 0; d < 64; d++) {
            float qv[4], kv[4];
            *(float4*)&qv[0] = *(float4*)&Qs[d * 64 + ty * 4];
            *(float4*)&kv[0] = *(float4*)&Ks[d * 64 + tx * 4];
#pragma unroll
            for (int i = 0; i < 4; i++)
#pragma unroll
                for (int j = 0; j < 4; j++) S[i][j] = fmaf(qv[i], kv[j], S[i][j]);
        }

        // online softmax per q row; row spread over the 16 tx lanes (half-warp)
#pragma unroll
        for (int i = 0; i < 4; i++) {
            float rmax = fmaxf(fmaxf(S[i][0], S[i][1]), fmaxf(S[i][2], S[i][3]));
#pragma unroll
            for (int off = 8; off; off >>= 1)
                rmax = fmaxf(rmax, __shfl_xor_sync(0xffffffffu, rmax, off));
            const float mnew = fmaxf(m_i[i], rmax);
            const float alpha = __expf(m_i[i] - mnew);
            float psum = 0.0f;
#pragma unroll
            for (int j = 0; j < 4; j++) {
                S[i][j] = __expf(S[i][j] - mnew);
                psum += S[i][j];
            }
#pragma unroll
            for (int off = 8; off; off >>= 1)
                psum += __shfl_xor_sync(0xffffffffu, psum, off);
            l_i[i] = l_i[i] * alpha + psum;
            m_i[i] = mnew;
#pragma unroll
            for (int j = 0; j < 4; j++) Oacc[i][j] *= alpha;
        }

        // write P transposed: Pts[k][q]
#pragma unroll
        for (int j = 0; j < 4; j++)
#pragma unroll
            for (int i = 0; i < 4; i++)
                Pts[(tx * 4 + j) * 68 + ty * 4 + i] = S[i][j];
        __syncthreads();

        // O[q][d] += sum_k P[q][k] * V[d][k]
#pragma unroll 8
        for (int k = 0; k < 64; k++) {
            float pv[4];
            *(float4*)&pv[0] = *(float4*)&Pts[k * 68 + ty * 4];
            float vv[4];
#pragma unroll
            for (int j = 0; j < 4; j++) vv[j] = Vs[(tx * 4 + j) * 65 + k];
#pragma unroll
            for (int i = 0; i < 4; i++)
#pragma unroll
                for (int j = 0; j < 4; j++) Oacc[i][j] = fmaf(pv[i], vv[j], Oacc[i][j]);
        }
        __syncthreads();
    }

    // stage O (normalized) into Vs as [d][q], then coalesced store
#pragma unroll
    for (int i = 0; i < 4; i++) {
        const float rinv = 1.0f / l_i[i];
#pragma unroll
        for (int j = 0; j < 4; j++)
            Vs[(tx * 4 + j) * 65 + ty * 4 + i] = Oacc[i][j] * rinv;
    }
    __syncthreads();

    float* Og = g_ctx + ((long)b * CC + h * DH) * TT;
    for (int i = tid; i < 64 * 16; i += 256) {
        const int r = i >> 4, c4 = (i & 15) << 2;
        float4 o;
        o.x = Vs[r * 65 + c4 + 0];
        o.y = Vs[r * 65 + c4 + 1];
        o.z = Vs[r * 65 + c4 + 2];
        o.w = Vs[r * 65 + c4 + 3];
        *(float4*)&Og[(long)r * TT + q0 + c4] = o;
    }
}

// ---------------------------------------------------------------------------
// LayerNorm over C per (b,t). Block (32,8): 32 t columns, 8-way c partition.
// ---------------------------------------------------------------------------
__global__ void __launch_bounds__(256) ln_kernel(
    const float* __restrict__ gamma, const float* __restrict__ beta,
    float* __restrict__ out)
{
    const int tx = threadIdx.x, ty = threadIdx.y;
    const int b = blockIdx.y;
    const int t = blockIdx.x * 32 + tx;
    const float* yb = g_y + (long)b * CC * TT;

    float s = 0.0f, s2 = 0.0f;
    for (int c = ty; c < CC; c += 8) {
        const float v = yb[(long)c * TT + t];
        s += v;
        s2 += v * v;
    }
    __shared__ float rs[8][32], rq[8][32], mu_s[32], rstd_s[32];
    rs[ty][tx] = s;
    rq[ty][tx] = s2;
    __syncthreads();
    if (ty == 0) {
        float S = 0.0f, S2 = 0.0f;
#pragma unroll
        for (int k = 0; k < 8; k++) { S += rs[k][tx]; S2 += rq[k][tx]; }
        const float mu = S * (1.0f / CC);
        const float var = S2 * (1.0f / CC) - mu * mu;
        mu_s[tx] = mu;
        rstd_s[tx] = rsqrtf(var + LN_EPS);
    }
    __syncthreads();
    const float mu = mu_s[tx], rstd = rstd_s[tx];
    float* ob = out + (long)b * CC * TT;
    for (int c = ty; c < CC; c += 8) {
        const float v = yb[(long)c * TT + t];
        ob[(long)c * TT + t] = (v - mu) * rstd * gamma[c] + beta[c];
    }
}

// ---------------------------------------------------------------------------
extern "C" void kernel_launch(void* const* d_in, const int* in_sizes, int n_in,
                              void* d_out, int out_size)
{
    const float* x     = (const float*)d_in[0];
    const float* wqkv  = (const float*)d_in[1];
    const float* wfc   = (const float*)d_in[2];
    const float* gamma = (const float*)d_in[3];
    const float* beta  = (const float*)d_in[4];
    float* out = (float*)d_out;

    float *qkv, *ctx, *y;
    cudaGetSymbolAddress((void**)&qkv, g_qkv);
    cudaGetSymbolAddress((void**)&ctx, g_ctx);
    cudaGetSymbolAddress((void**)&y, g_y);

    // 1) QKV = w_qkv @ x[b]
    sgemm_kernel<false><<<dim3(TT / 128, 3 * CC / 128, BB), 256>>>(
        wqkv, x, nullptr, qkv, 3 * CC, TT, CC,
        (long)CC * TT, (long)3 * CC * TT, 0);

    // 2) attention -> g_ctx
    cudaFuncSetAttribute(attn_kernel, cudaFuncAttributeMaxDynamicSharedMemorySize, ATTN_SMEM);
    attn_kernel<<<dim3(TT / 64, HH, BB), 256, ATTN_SMEM>>>();

    // 3) y = w_fc @ ctx[b] + x[b]
    sgemm_kernel<true><<<dim3(TT / 128, CC / 128, BB), 256>>>(
        wfc, ctx, x, y, CC, TT, CC,
        (long)CC * TT, (long)CC * TT, (long)CC * TT);

    // 4) LayerNorm -> out
    ln_kernel<<<dim3(TT / 32, BB), dim3(32, 8)>>>(gamma, beta, out);
}

// round 3
// speedup vs baseline: 1.4060x; 1.4060x over previous
#include <cuda_runtime.h>
#include <cuda_bf16.h>
#include <cstdint>

#define BB 2
#define CC 1024
#define TT 2048
#define HH 16
#define DH 64
#define LN_EPS 1e-6f

// ---- GEMM tiling (mma.sync path) ----
#define GM_MT 128
#define GM_NT 128
#define GM_KC 32
#define NCHUNK (CC / GM_KC)            // 32
#define PITCH 40                        // bf16 elems per smem row (32 + 8 pad)
#define A_BYTES (GM_MT * PITCH * 2)     // 10240
#define B_BYTES (GM_NT * PITCH * 2)     // 10240
#define STAGE_BYTES (2 * A_BYTES + 2 * B_BYTES)  // 40960 (A hi/lo + B hi/lo)
#define GEMM_SMEM (2 * STAGE_BYTES)     // 81920

// ---- scratch (device globals; no allocations allowed) ----
__device__ float g_qkv[(size_t)BB * 3 * CC * TT];   // [b][3C][T]
__device__ float g_ctx[(size_t)BB * CC * TT];       // [b][C][T]
__device__ float g_y[(size_t)BB * CC * TT];         // pre-LN
__device__ __nv_bfloat16 g_wqkv_hi[3 * CC * CC], g_wqkv_lo[3 * CC * CC];
__device__ __nv_bfloat16 g_wfc_hi[CC * CC], g_wfc_lo[CC * CC];
__device__ __nv_bfloat16 g_xT_hi[(size_t)BB * TT * CC], g_xT_lo[(size_t)BB * TT * CC];
__device__ __nv_bfloat16 g_cT_hi[(size_t)BB * TT * CC], g_cT_lo[(size_t)BB * TT * CC];

// ===========================================================================
// PTX helpers (portable sm_80+ subset only — NO tcgen05 on this toolchain)
// ===========================================================================
__device__ __forceinline__ uint32_t smem_u32(const void* p) {
    return (uint32_t)__cvta_generic_to_shared(p);
}
__device__ __forceinline__ void cp16(uint32_t dst, const void* src) {
    asm volatile("cp.async.cg.shared.global [%0], [%1], 16;\n" :: "r"(dst), "l"(src));
}
__device__ __forceinline__ void cp_commit() {
    asm volatile("cp.async.commit_group;\n" ::: "memory");
}
__device__ __forceinline__ void ldmatrix_x4(uint32_t& a0, uint32_t& a1, uint32_t& a2,
                                            uint32_t& a3, uint32_t addr) {
    asm volatile("ldmatrix.sync.aligned.m8n8.x4.shared.b16 {%0,%1,%2,%3}, [%4];"
                 : "=r"(a0), "=r"(a1), "=r"(a2), "=r"(a3) : "r"(addr));
}
__device__ __forceinline__ void ldmatrix_x2(uint32_t& b0, uint32_t& b1, uint32_t addr) {
    asm volatile("ldmatrix.sync.aligned.m8n8.x2.shared.b16 {%0,%1}, [%2];"
                 : "=r"(b0), "=r"(b1) : "r"(addr));
}
__device__ __forceinline__ void mma_bf16(float& c0, float& c1, float& c2, float& c3,
                                         uint32_t a0, uint32_t a1, uint32_t a2, uint32_t a3,
                                         uint32_t b0, uint32_t b1) {
    asm volatile(
        "mma.sync.aligned.m16n8k16.row.col.f32.bf16.bf16.f32 "
        "{%0,%1,%2,%3}, {%4,%5,%6,%7}, {%8,%9}, {%0,%1,%2,%3};"
        : "+f"(c0), "+f"(c1), "+f"(c2), "+f"(c3)
        : "r"(a0), "r"(a1), "r"(a2), "r"(a3), "r"(b0), "r"(b1));
}

// ===========================================================================
// Split / transpose conversion kernels
// ===========================================================================
__global__ void __launch_bounds__(256) split_kernel(
    const float* __restrict__ in, __nv_bfloat16* __restrict__ hi,
    __nv_bfloat16* __restrict__ lo, int n)
{
    int i = blockIdx.x * 256 + threadIdx.x;
    if (i < n) {
        const float v = in[i];
        const __nv_bfloat16 h = __float2bfloat16(v);
        hi[i] = h;
        lo[i] = __float2bfloat16(v - __bfloat162float(h));
    }
}

// in [C,T] fp32 (batched) -> out [T,C] bf16 hi/lo
__global__ void __launch_bounds__(256) tsplit_kernel(
    const float* __restrict__ in, __nv_bfloat16* __restrict__ hi,
    __nv_bfloat16* __restrict__ lo)
{
    __shared__ float tile[32][33];
    const int b = blockIdx.z;
    const int t0 = blockIdx.x * 32, c0 = blockIdx.y * 32;
    const float* ib = in + (size_t)b * CC * TT;
    for (int j = threadIdx.y; j < 32; j += 8)
        tile[j][threadIdx.x] = ib[(size_t)(c0 + j) * TT + t0 + threadIdx.x];
    __syncthreads();
    __nv_bfloat16* hb = hi + (size_t)b * TT * CC;
    __nv_bfloat16* lb = lo + (size_t)b * TT * CC;
    for (int j = threadIdx.y; j < 32; j += 8) {
        const float v = tile[threadIdx.x][j];
        const __nv_bfloat16 h = __float2bfloat16(v);
        const size_t o = (size_t)(t0 + j) * CC + c0 + threadIdx.x;
        hb[o] = h;
        lb[o] = __float2bfloat16(v - __bfloat162float(h));
    }
}

// ===========================================================================
// mma.sync bf16-split GEMM: C[M,N](fp32) = A[M,K] @ B[N,K]^T (+residual)
// Block 128x128, 8 warps (2m x 4n), warp tile 64x32, K-chunk 32, 2 stages.
// ===========================================================================
__device__ __forceinline__ void g_load_stage(
    uint32_t st, int kc,
    const __nv_bfloat16* __restrict__ Ahi, const __nv_bfloat16* __restrict__ Alo,
    const __nv_bfloat16* __restrict__ Bhi, const __nv_bfloat16* __restrict__ Blo,
    int m0, int n0, int tid)
{
    // A: 128 rows x 4 chunks of 16B (8 bf16)
    for (int i = tid; i < GM_MT * 4; i += 256) {
        const int r = i >> 2, c = i & 3;
        const uint32_t dst = st + (uint32_t)(r * PITCH + c * 8) * 2;
        const size_t g = (size_t)(m0 + r) * CC + kc + c * 8;
        cp16(dst, Ahi + g);
        cp16(dst + A_BYTES, Alo + g);
    }
    // B: 128 rows x 4 chunks
    for (int i = tid; i < GM_NT * 4; i += 256) {
        const int r = i >> 2, c = i & 3;
        const uint32_t dst = st + 2 * A_BYTES + (uint32_t)(r * PITCH + c * 8) * 2;
        const size_t g = (size_t)(n0 + r) * CC + kc + c * 8;
        cp16(dst, Bhi + g);
        cp16(dst + B_BYTES, Blo + g);
    }
    cp_commit();
}

template <bool RES>
__global__ void __launch_bounds__(256) hgemm(
    const __nv_bfloat16* __restrict__ Ahi, const __nv_bfloat16* __restrict__ Alo,
    const __nv_bfloat16* __restrict__ BhiAll, const __nv_bfloat16* __restrict__ BloAll,
    const float* __restrict__ Res, float* __restrict__ Cout, long outBatchStride)
{
    extern __shared__ char smem[];
    const uint32_t sbase = smem_u32(smem);

    const int tid = threadIdx.x;
    const int wid = tid >> 5;
    const int lane = tid & 31;
    const int b = blockIdx.z;
    const int m0 = blockIdx.y * GM_MT;
    const int n0 = blockIdx.x * GM_NT;
    const int wm = (wid >> 2) * 64;   // warp m offset in tile
    const int wn = (wid & 3) * 32;    // warp n offset in tile

    const __nv_bfloat16* Bhi = BhiAll + (size_t)b * TT * CC;
    const __nv_bfloat16* Blo = BloAll + (size_t)b * TT * CC;

    float acc[4][4][4];
#pragma unroll
    for (int i = 0; i < 4; i++)
#pragma unroll
        for (int j = 0; j < 4; j++)
#pragma unroll
            for (int r = 0; r < 4; r++) acc[i][j][r] = 0.0f;

    // precompute ldmatrix lane addressing (byte offsets within a tile)
    const int a_row = lane & 15;             // 0..15
    const int a_ksel = (lane >> 4) * 8;      // 0 or 8
    const int b_row = lane & 7;              // 0..7
    const int b_ksel = ((lane >> 3) & 1) * 8;

    g_load_stage(sbase, 0, Ahi, Alo, Bhi, Blo, m0, n0, tid);

    for (int c = 0; c < NCHUNK; c++) {
        const uint32_t st = sbase + (uint32_t)(c & 1) * STAGE_BYTES;
        if (c + 1 < NCHUNK) {
            g_load_stage(sbase + (uint32_t)((c + 1) & 1) * STAGE_BYTES,
                         (c + 1) * GM_KC, Ahi, Alo, Bhi, Blo, m0, n0, tid);
            asm volatile("cp.async.wait_group 1;\n" ::: "memory");
        } else {
            asm volatile("cp.async.wait_group 0;\n" ::: "memory");
        }
        __syncthreads();

        const uint32_t sAh = st;
        const uint32_t sAl = st + A_BYTES;
        const uint32_t sBh = st + 2 * A_BYTES;
        const uint32_t sBl = st + 2 * A_BYTES + B_BYTES;

#pragma unroll
        for (int kk = 0; kk < GM_KC; kk += 16) {
            uint32_t ah[4][4], al[4][4], bh[4][2], bl[4][2];
#pragma unroll
            for (int mi = 0; mi < 4; mi++) {
                const uint32_t off =
                    (uint32_t)((wm + mi * 16 + a_row) * PITCH + kk + a_ksel) * 2;
                ldmatrix_x4(ah[mi][0], ah[mi][1], ah[mi][2], ah[mi][3], sAh + off);
                ldmatrix_x4(al[mi][0], al[mi][1], al[mi][2], al[mi][3], sAl + off);
            }
#pragma unroll
            for (int nj = 0; nj < 4; nj++) {
                const uint32_t off =
                    (uint32_t)((wn + nj * 8 + b_row) * PITCH + kk + b_ksel) * 2;
                ldmatrix_x2(bh[nj][0], bh[nj][1], sBh + off);
                ldmatrix_x2(bl[nj][0], bl[nj][1], sBl + off);
            }
#pragma unroll
            for (int mi = 0; mi < 4; mi++)
#pragma unroll
                for (int nj = 0; nj < 4; nj++) {
                    float* a = acc[mi][nj];
                    mma_bf16(a[0], a[1], a[2], a[3],
                             ah[mi][0], ah[mi][1], ah[mi][2], ah[mi][3],
                             bh[nj][0], bh[nj][1]);
                    mma_bf16(a[0], a[1], a[2], a[3],
                             ah[mi][0], ah[mi][1], ah[mi][2], ah[mi][3],
                             bl[nj][0], bl[nj][1]);
                    mma_bf16(a[0], a[1], a[2], a[3],
                             al[mi][0], al[mi][1], al[mi][2], al[mi][3],
                             bh[nj][0], bh[nj][1]);
                }
        }
        __syncthreads();
    }

    // epilogue: thread (t) in tile (mi,nj): rows m+t/4, m+t/4+8; cols n+2(t%4)
    const int er = lane >> 2;        // 0..7
    const int ec = (lane & 3) * 2;   // 0,2,4,6
    float* Cb = Cout + (size_t)b * outBatchStride;
    const float* Rb = RES ? (Res + (size_t)b * CC * TT) : nullptr;
#pragma unroll
    for (int mi = 0; mi < 4; mi++) {
#pragma unroll
        for (int nj = 0; nj < 4; nj++) {
            const int m = m0 + wm + mi * 16 + er;
            const int n = n0 + wn + nj * 8 + ec;
            float2 v0 = make_float2(acc[mi][nj][0], acc[mi][nj][1]);
            float2 v1 = make_float2(acc[mi][nj][2], acc[mi][nj][3]);
            if (RES) {
                const float2 r0 = *(const float2*)(Rb + (size_t)m * TT + n);
                const float2 r1 = *(const float2*)(Rb + (size_t)(m + 8) * TT + n);
                v0.x += r0.x; v0.y += r0.y;
                v1.x += r1.x; v1.y += r1.y;
            }
            *(float2*)(Cb + (size_t)m * TT + n) = v0;
            *(float2*)(Cb + (size_t)(m + 8) * TT + n) = v1;
        }
    }
}

// ===========================================================================
// Flash-style attention (unchanged, known good)
// ===========================================================================
#define SM_QS 0
#define SM_KS (64 * 64)
#define SM_PT (2 * 64 * 64)
#define SM_VS (2 * 64 * 64 + 64 * 68)
#define ATTN_SMEM ((2 * 64 * 64 + 64 * 68 + 64 * 65) * 4)

__global__ void __launch_bounds__(256) attn_kernel()
{
    extern __shared__ float sm[];
    float* Qs = sm + SM_QS;
    float* Ks = sm + SM_KS;
    float* Pts = sm + SM_PT;   // pitch 68
    float* Vs = sm + SM_VS;    // pitch 65

    const int tid = threadIdx.x;
    const int tx = tid & 15;
    const int ty = tid >> 4;
    const int b = blockIdx.z, h = blockIdx.y;
    const int q0 = blockIdx.x * 64;

    const float* Qg = g_qkv + ((long)b * 3 * CC + h * DH) * TT;
    const float* Kg = Qg + (long)CC * TT;
    const float* Vg = Qg + 2L * CC * TT;

    for (int i = tid; i < 64 * 16; i += 256) {
        const int r = i >> 4, c4 = (i & 15) << 2;
        *(float4*)&Qs[r * 64 + c4] = *(const float4*)&Qg[(long)r * TT + q0 + c4];
    }

    float m_i[4], l_i[4], Oacc[4][4];
#pragma unroll
    for (int i = 0; i < 4; i++) {
        m_i[i] = -__int_as_float(0x7f800000);
        l_i[i] = 0.0f;
#pragma unroll
        for (int j = 0; j < 4; j++) Oacc[i][j] = 0.0f;
    }
    __syncthreads();

    for (int k0 = 0; k0 < TT; k0 += 64) {
        for (int i = tid; i < 64 * 16; i += 256) {
            const int r = i >> 4, c4 = (i & 15) << 2;
            *(float4*)&Ks[r * 64 + c4] = *(const float4*)&Kg[(long)r * TT + k0 + c4];
            const float4 v = *(const float4*)&Vg[(long)r * TT + k0 + c4];
            Vs[r * 65 + c4 + 0] = v.x;
            Vs[r * 65 + c4 + 1] = v.y;
            Vs[r * 65 + c4 + 2] = v.z;
            Vs[r * 65 + c4 + 3] = v.w;
        }
        __syncthreads();

        float S[4][4];
#pragma unroll
        for (int i = 0; i < 4; i++)
#pragma unroll
            for (int j = 0; j < 4; j++) S[i][j] = 0.0f;
#pragma unroll 8
        for (int d = 0; d < 64; d++) {
            float qv[4], kv[4];
            *(float4*)&qv[0] = *(float4*)&Qs[d * 64 + ty * 4];
            *(float4*)&kv[0] = *(float4*)&Ks[d * 64 + tx * 4];
#pragma unroll
            for (int i = 0; i < 4; i++)
#pragma unroll
                for (int j = 0; j < 4; j++) S[i][j] = fmaf(qv[i], kv[j], S[i][j]);
        }

#pragma unroll
        for (int i = 0; i < 4; i++) {
            float rmax = fmaxf(fmaxf(S[i][0], S[i][1]), fmaxf(S[i][2], S[i][3]));
#pragma unroll
            for (int off = 8; off; off >>= 1)
                rmax = fmaxf(rmax, __shfl_xor_sync(0xffffffffu, rmax, off));
            const float mnew = fmaxf(m_i[i], rmax);
            const float alpha = __expf(m_i[i] - mnew);
            float psum = 0.0f;
#pragma unroll
            for (int j = 0; j < 4; j++) {
                S[i][j] = __expf(S[i][j] - mnew);
                psum += S[i][j];
            }
#pragma unroll
            for (int off = 8; off; off >>= 1)
                psum += __shfl_xor_sync(0xffffffffu, psum, off);
            l_i[i] = l_i[i] * alpha + psum;
            m_i[i] = mnew;
#pragma unroll
            for (int j = 0; j < 4; j++) Oacc[i][j] *= alpha;
        }

#pragma unroll
        for (int j = 0; j < 4; j++)
#pragma unroll
            for (int i = 0; i < 4; i++)
                Pts[(tx * 4 + j) * 68 + ty * 4 + i] = S[i][j];
        __syncthreads();

#pragma unroll 8
        for (int k = 0; k < 64; k++) {
            float pv[4];
            *(float4*)&pv[0] = *(float4*)&Pts[k * 68 + ty * 4];
            float vv[4];
#pragma unroll
            for (int j = 0; j < 4; j++) vv[j] = Vs[(tx * 4 + j) * 65 + k];
#pragma unroll
            for (int i = 0; i < 4; i++)
#pragma unroll
                for (int j = 0; j < 4; j++) Oacc[i][j] = fmaf(pv[i], vv[j], Oacc[i][j]);
        }
        __syncthreads();
    }

#pragma unroll
    for (int i = 0; i < 4; i++) {
        const float rinv = 1.0f / l_i[i];
#pragma unroll
        for (int j = 0; j < 4; j++)
            Vs[(tx * 4 + j) * 65 + ty * 4 + i] = Oacc[i][j] * rinv;
    }
    __syncthreads();

    float* Og = g_ctx + ((long)b * CC + h * DH) * TT;
    for (int i = tid; i < 64 * 16; i += 256) {
        const int r = i >> 4, c4 = (i & 15) << 2;
        float4 o;
        o.x = Vs[r * 65 + c4 + 0];
        o.y = Vs[r * 65 + c4 + 1];
        o.z = Vs[r * 65 + c4 + 2];
        o.w = Vs[r * 65 + c4 + 3];
        *(float4*)&Og[(long)r * TT + q0 + c4] = o;
    }
}

// ===========================================================================
// LayerNorm (unchanged)
// ===========================================================================
__global__ void __launch_bounds__(256) ln_kernel(
    const float* __restrict__ gamma, const float* __restrict__ beta,
    float* __restrict__ out)
{
    const int tx = threadIdx.x, ty = threadIdx.y;
    const int b = blockIdx.y;
    const int t = blockIdx.x * 32 + tx;
    const float* yb = g_y + (long)b * CC * TT;

    float s = 0.0f, s2 = 0.0f;
    for (int c = ty; c < CC; c += 8) {
        const float v = yb[(long)c * TT + t];
        s += v;
        s2 += v * v;
    }
    __shared__ float rs[8][32], rq[8][32], mu_s[32], rstd_s[32];
    rs[ty][tx] = s;
    rq[ty][tx] = s2;
    __syncthreads();
    if (ty == 0) {
        float S = 0.0f, S2 = 0.0f;
#pragma unroll
        for (int k = 0; k < 8; k++) { S += rs[k][tx]; S2 += rq[k][tx]; }
        const float mu = S * (1.0f / CC);
        const float var = S2 * (1.0f / CC) - mu * mu;
        mu_s[tx] = mu;
        rstd_s[tx] = rsqrtf(var + LN_EPS);
    }
    __syncthreads();
    const float mu = mu_s[tx], rstd = rstd_s[tx];
    float* ob = out + (long)b * CC * TT;
    for (int c = ty; c < CC; c += 8) {
        const float v = yb[(long)c * TT + t];
        ob[(long)c * TT + t] = (v - mu) * rstd * gamma[c] + beta[c];
    }
}

// ===========================================================================
extern "C" void kernel_launch(void* const* d_in, const int* in_sizes, int n_in,
                              void* d_out, int out_size)
{
    const float* x     = (const float*)d_in[0];
    const float* wqkv  = (const float*)d_in[1];
    const float* wfc   = (const float*)d_in[2];
    const float* gamma = (const float*)d_in[3];
    const float* beta  = (const float*)d_in[4];
    float* out = (float*)d_out;

    float *qkv, *ctx, *y;
    cudaGetSymbolAddress((void**)&qkv, g_qkv);
    cudaGetSymbolAddress((void**)&ctx, g_ctx);
    cudaGetSymbolAddress((void**)&y, g_y);
    __nv_bfloat16 *wqh, *wql, *wfh, *wfl, *xth, *xtl, *cth, *ctl;
    cudaGetSymbolAddress((void**)&wqh, g_wqkv_hi);
    cudaGetSymbolAddress((void**)&wql, g_wqkv_lo);
    cudaGetSymbolAddress((void**)&wfh, g_wfc_hi);
    cudaGetSymbolAddress((void**)&wfl, g_wfc_lo);
    cudaGetSymbolAddress((void**)&xth, g_xT_hi);
    cudaGetSymbolAddress((void**)&xtl, g_xT_lo);
    cudaGetSymbolAddress((void**)&cth, g_cT_hi);
    cudaGetSymbolAddress((void**)&ctl, g_cT_lo);

    cudaFuncSetAttribute(hgemm<false>, cudaFuncAttributeMaxDynamicSharedMemorySize, GEMM_SMEM);
    cudaFuncSetAttribute(hgemm<true>, cudaFuncAttributeMaxDynamicSharedMemorySize, GEMM_SMEM);
    cudaFuncSetAttribute(attn_kernel, cudaFuncAttributeMaxDynamicSharedMemorySize, ATTN_SMEM);

    // 0) precision-split conversions
    split_kernel<<<(3 * CC * CC + 255) / 256, 256>>>(wqkv, wqh, wql, 3 * CC * CC);
    split_kernel<<<(CC * CC + 255) / 256, 256>>>(wfc, wfh, wfl, CC * CC);
    tsplit_kernel<<<dim3(TT / 32, CC / 32, BB), dim3(32, 8)>>>(x, xth, xtl);

    // 1) QKV = w_qkv @ x  (mma.sync bf16-split)
    hgemm<false><<<dim3(TT / GM_NT, 3 * CC / GM_MT, BB), 256, GEMM_SMEM>>>(
        wqh, wql, xth, xtl, nullptr, qkv, (long)3 * CC * TT);

    // 2) attention -> g_ctx
    attn_kernel<<<dim3(TT / 64, HH, BB), 256, ATTN_SMEM>>>();

    // 3) split-transpose ctx
    tsplit_kernel<<<dim3(TT / 32, CC / 32, BB), dim3(32, 8)>>>(ctx, cth, ctl);

    // 4) y = w_fc @ ctx + x  (fused residual)
    hgemm<true><<<dim3(TT / GM_NT, CC / GM_MT, BB), 256, GEMM_SMEM>>>(
        wfh, wfl, cth, ctl, x, y, (long)CC * TT);

    // 5) LayerNorm -> out
    ln_kernel<<<dim3(TT / 32, BB), dim3(32, 8)>>>(gamma, beta, out);
}

// round 4
// speedup vs baseline: 2.6784x; 1.9050x over previous
#include <cuda_runtime.h>
#include <cuda_bf16.h>
#include <cstdint>

#define BB 2
#define CC 1024
#define TT 2048
#define HH 16
#define DH 64
#define LN_EPS 1e-6f

// ---- dense GEMM tiling (mma.sync path) ----
#define GM_MT 128
#define GM_NT 128
#define GM_KC 32
#define NCHUNK (CC / GM_KC)            // 32
#define PITCH 40                        // bf16 elems per smem row (32 + 8 pad)
#define A_BYTES (GM_MT * PITCH * 2)     // 10240
#define B_BYTES (GM_NT * PITCH * 2)     // 10240
#define STAGE_BYTES (2 * A_BYTES + 2 * B_BYTES)  // 40960
#define GEMM_SMEM (2 * STAGE_BYTES)     // 81920

// ---- attention tiling ----
#define QPITCH 72                       // bf16 pitch for 64-wide rows (144B)
#define VPITCH 136                      // bf16 pitch for 128-wide rows (272B)
#define AQ_B (128 * QPITCH * 2)         // 18432 (one Q/K buffer)
#define AV_B (64 * VPITCH * 2)          // 17408 (one V buffer)
#define ASTAGE_B (2 * AQ_B + 2 * AV_B)  // 71680 (K hi/lo + V hi/lo)
#define ATTN_SMEM (2 * AQ_B + 2 * ASTAGE_B)  // 180224

// ---- scratch (device globals; no allocations allowed) ----
__device__ float g_qkv[(size_t)BB * 3 * CC * TT];   // [b][3C][T]
__device__ float g_y[(size_t)BB * CC * TT];         // pre-LN
__device__ __nv_bfloat16 g_wqkv_hi[3 * CC * CC], g_wqkv_lo[3 * CC * CC];
__device__ __nv_bfloat16 g_wfc_hi[CC * CC], g_wfc_lo[CC * CC];
__device__ __nv_bfloat16 g_xT_hi[(size_t)BB * TT * CC], g_xT_lo[(size_t)BB * TT * CC];
__device__ __nv_bfloat16 g_cT_hi[(size_t)BB * TT * CC], g_cT_lo[(size_t)BB * TT * CC];
// attention operand layouts
__device__ __nv_bfloat16 g_qT_hi[(size_t)BB * HH * TT * DH], g_qT_lo[(size_t)BB * HH * TT * DH];
__device__ __nv_bfloat16 g_kT_hi[(size_t)BB * HH * TT * DH], g_kT_lo[(size_t)BB * HH * TT * DH];
__device__ __nv_bfloat16 g_v_hi[(size_t)BB * HH * DH * TT], g_v_lo[(size_t)BB * HH * DH * TT];

// ===========================================================================
// PTX helpers (portable sm_80+ subset only)
// ===========================================================================
__device__ __forceinline__ uint32_t smem_u32(const void* p) {
    return (uint32_t)__cvta_generic_to_shared(p);
}
__device__ __forceinline__ void cp16(uint32_t dst, const void* src) {
    asm volatile("cp.async.cg.shared.global [%0], [%1], 16;\n" :: "r"(dst), "l"(src));
}
__device__ __forceinline__ void cp_commit() {
    asm volatile("cp.async.commit_group;\n" ::: "memory");
}
__device__ __forceinline__ void ldmatrix_x4(uint32_t& a0, uint32_t& a1, uint32_t& a2,
                                            uint32_t& a3, uint32_t addr) {
    asm volatile("ldmatrix.sync.aligned.m8n8.x4.shared.b16 {%0,%1,%2,%3}, [%4];"
                 : "=r"(a0), "=r"(a1), "=r"(a2), "=r"(a3) : "r"(addr));
}
__device__ __forceinline__ void ldmatrix_x2(uint32_t& b0, uint32_t& b1, uint32_t addr) {
    asm volatile("ldmatrix.sync.aligned.m8n8.x2.shared.b16 {%0,%1}, [%2];"
                 : "=r"(b0), "=r"(b1) : "r"(addr));
}
__device__ __forceinline__ void mma_bf16(float* c,
                                         uint32_t a0, uint32_t a1, uint32_t a2, uint32_t a3,
                                         uint32_t b0, uint32_t b1) {
    asm volatile(
        "mma.sync.aligned.m16n8k16.row.col.f32.bf16.bf16.f32 "
        "{%0,%1,%2,%3}, {%4,%5,%6,%7}, {%8,%9}, {%0,%1,%2,%3};"
        : "+f"(c[0]), "+f"(c[1]), "+f"(c[2]), "+f"(c[3])
        : "r"(a0), "r"(a1), "r"(a2), "r"(a3), "r"(b0), "r"(b1));
}
__device__ __forceinline__ uint32_t cvt2(float f0, float f1) {  // lo=f0, hi=f1
    uint32_t r;
    asm("cvt.rn.bf16x2.f32 %0, %1, %2;" : "=r"(r) : "f"(f1), "f"(f0));
    return r;
}
__device__ __forceinline__ void split2(float f0, float f1, uint32_t& hi, uint32_t& lo) {
    hi = cvt2(f0, f1);
    const float h0 = __uint_as_float(hi << 16);
    const float h1 = __uint_as_float(hi & 0xffff0000u);
    lo = cvt2(f0 - h0, f1 - h1);
}

// ===========================================================================
// Split / transpose conversion kernels
// ===========================================================================
__global__ void __launch_bounds__(256) split_kernel(
    const float* __restrict__ in, __nv_bfloat16* __restrict__ hi,
    __nv_bfloat16* __restrict__ lo, int n)
{
    int i = blockIdx.x * 256 + threadIdx.x;
    if (i < n) {
        const float v = in[i];
        const __nv_bfloat16 h = __float2bfloat16(v);
        hi[i] = h;
        lo[i] = __float2bfloat16(v - __bfloat162float(h));
    }
}

// in [C,T] fp32 (batched) -> out [T,C] bf16 hi/lo
__global__ void __launch_bounds__(256) tsplit_kernel(
    const float* __restrict__ in, __nv_bfloat16* __restrict__ hi,
    __nv_bfloat16* __restrict__ lo)
{
    __shared__ float tile[32][33];
    const int b = blockIdx.z;
    const int t0 = blockIdx.x * 32, c0 = blockIdx.y * 32;
    const float* ib = in + (size_t)b * CC * TT;
    for (int j = threadIdx.y; j < 32; j += 8)
        tile[j][threadIdx.x] = ib[(size_t)(c0 + j) * TT + t0 + threadIdx.x];
    __syncthreads();
    __nv_bfloat16* hb = hi + (size_t)b * TT * CC;
    __nv_bfloat16* lb = lo + (size_t)b * TT * CC;
    for (int j = threadIdx.y; j < 32; j += 8) {
        const float v = tile[threadIdx.x][j];
        const __nv_bfloat16 h = __float2bfloat16(v);
        const size_t o = (size_t)(t0 + j) * CC + c0 + threadIdx.x;
        hb[o] = h;
        lb[o] = __float2bfloat16(v - __bfloat162float(h));
    }
}

// g_qkv fp32 -> attention operand layouts (Q^T,K^T [bh][T][64]; V [bh][64][T])
__global__ void __launch_bounds__(256) qkv_split_kernel()
{
    __shared__ float tq[32][33], tk[32][33];
    const int tx = threadIdx.x, ty = threadIdx.y;
    const int z = blockIdx.z;          // bh
    const int b = z >> 4, h = z & 15;
    const int c0 = blockIdx.y * 32;    // channel within head (0 or 32)
    const int t0 = blockIdx.x * 32;

    const float* base = g_qkv + (size_t)b * 3 * CC * TT;
    const float* Qp = base + (size_t)(h * DH + c0) * TT;
    const float* Kp = base + (size_t)(CC + h * DH + c0) * TT;
    const float* Vp = base + (size_t)(2 * CC + h * DH + c0) * TT;

    for (int j = ty; j < 32; j += 8) {
        tq[j][tx] = Qp[(size_t)j * TT + t0 + tx];
        tk[j][tx] = Kp[(size_t)j * TT + t0 + tx];
        // V: no transpose
        const float v = Vp[(size_t)j * TT + t0 + tx];
        const __nv_bfloat16 vh = __float2bfloat16(v);
        const size_t vi = ((size_t)z * DH + c0 + j) * TT + t0 + tx;
        g_v_hi[vi] = vh;
        g_v_lo[vi] = __float2bfloat16(v - __bfloat162float(vh));
    }
    __syncthreads();
    for (int j = ty; j < 32; j += 8) {
        const size_t o = ((size_t)z * TT + t0 + j) * DH + c0 + tx;
        const float q = tq[tx][j];
        const __nv_bfloat16 qh = __float2bfloat16(q);
        g_qT_hi[o] = qh;
        g_qT_lo[o] = __float2bfloat16(q - __bfloat162float(qh));
        const float k = tk[tx][j];
        const __nv_bfloat16 kh = __float2bfloat16(k);
        g_kT_hi[o] = kh;
        g_kT_lo[o] = __float2bfloat16(k - __bfloat162float(kh));
    }
}

// ===========================================================================
// mma.sync bf16-split dense GEMM (unchanged, known good)
// ===========================================================================
__device__ __forceinline__ void g_load_stage(
    uint32_t st, int kc,
    const __nv_bfloat16* __restrict__ Ahi, const __nv_bfloat16* __restrict__ Alo,
    const __nv_bfloat16* __restrict__ Bhi, const __nv_bfloat16* __restrict__ Blo,
    int m0, int n0, int tid)
{
    for (int i = tid; i < GM_MT * 4; i += 256) {
        const int r = i >> 2, c = i & 3;
        const uint32_t dst = st + (uint32_t)(r * PITCH + c * 8) * 2;
        const size_t g = (size_t)(m0 + r) * CC + kc + c * 8;
        cp16(dst, Ahi + g);
        cp16(dst + A_BYTES, Alo + g);
    }
    for (int i = tid; i < GM_NT * 4; i += 256) {
        const int r = i >> 2, c = i & 3;
        const uint32_t dst = st + 2 * A_BYTES + (uint32_t)(r * PITCH + c * 8) * 2;
        const size_t g = (size_t)(n0 + r) * CC + kc + c * 8;
        cp16(dst, Bhi + g);
        cp16(dst + B_BYTES, Blo + g);
    }
    cp_commit();
}

template <bool RES>
__global__ void __launch_bounds__(256) hgemm(
    const __nv_bfloat16* __restrict__ Ahi, const __nv_bfloat16* __restrict__ Alo,
    const __nv_bfloat16* __restrict__ BhiAll, const __nv_bfloat16* __restrict__ BloAll,
    const float* __restrict__ Res, float* __restrict__ Cout, long outBatchStride)
{
    extern __shared__ char smem[];
    const uint32_t sbase = smem_u32(smem);

    const int tid = threadIdx.x;
    const int wid = tid >> 5;
    const int lane = tid & 31;
    const int b = blockIdx.z;
    const int m0 = blockIdx.y * GM_MT;
    const int n0 = blockIdx.x * GM_NT;
    const int wm = (wid >> 2) * 64;
    const int wn = (wid & 3) * 32;

    const __nv_bfloat16* Bhi = BhiAll + (size_t)b * TT * CC;
    const __nv_bfloat16* Blo = BloAll + (size_t)b * TT * CC;

    float acc[4][4][4];
#pragma unroll
    for (int i = 0; i < 4; i++)
#pragma unroll
        for (int j = 0; j < 4; j++)
#pragma unroll
            for (int r = 0; r < 4; r++) acc[i][j][r] = 0.0f;

    const int a_row = lane & 15;
    const int a_ksel = (lane >> 4) * 8;
    const int b_row = lane & 7;
    const int b_ksel = ((lane >> 3) & 1) * 8;

    g_load_stage(sbase, 0, Ahi, Alo, Bhi, Blo, m0, n0, tid);

    for (int c = 0; c < NCHUNK; c++) {
        const uint32_t st = sbase + (uint32_t)(c & 1) * STAGE_BYTES;
        if (c + 1 < NCHUNK) {
            g_load_stage(sbase + (uint32_t)((c + 1) & 1) * STAGE_BYTES,
                         (c + 1) * GM_KC, Ahi, Alo, Bhi, Blo, m0, n0, tid);
            asm volatile("cp.async.wait_group 1;\n" ::: "memory");
        } else {
            asm volatile("cp.async.wait_group 0;\n" ::: "memory");
        }
        __syncthreads();

        const uint32_t sAh = st;
        const uint32_t sAl = st + A_BYTES;
        const uint32_t sBh = st + 2 * A_BYTES;
        const uint32_t sBl = st + 2 * A_BYTES + B_BYTES;

#pragma unroll
        for (int kk = 0; kk < GM_KC; kk += 16) {
            uint32_t ah[4][4], al[4][4], bh[4][2], bl[4][2];
#pragma unroll
            for (int mi = 0; mi < 4; mi++) {
                const uint32_t off =
                    (uint32_t)((wm + mi * 16 + a_row) * PITCH + kk + a_ksel) * 2;
                ldmatrix_x4(ah[mi][0], ah[mi][1], ah[mi][2], ah[mi][3], sAh + off);
                ldmatrix_x4(al[mi][0], al[mi][1], al[mi][2], al[mi][3], sAl + off);
            }
#pragma unroll
            for (int nj = 0; nj < 4; nj++) {
                const uint32_t off =
                    (uint32_t)((wn + nj * 8 + b_row) * PITCH + kk + b_ksel) * 2;
                ldmatrix_x2(bh[nj][0], bh[nj][1], sBh + off);
                ldmatrix_x2(bl[nj][0], bl[nj][1], sBl + off);
            }
#pragma unroll
            for (int mi = 0; mi < 4; mi++)
#pragma unroll
                for (int nj = 0; nj < 4; nj++) {
                    float* a = acc[mi][nj];
                    mma_bf16(a, ah[mi][0], ah[mi][1], ah[mi][2], ah[mi][3],
                             bh[nj][0], bh[nj][1]);
                    mma_bf16(a, ah[mi][0], ah[mi][1], ah[mi][2], ah[mi][3],
                             bl[nj][0], bl[nj][1]);
                    mma_bf16(a, al[mi][0], al[mi][1], al[mi][2], al[mi][3],
                             bh[nj][0], bh[nj][1]);
                }
        }
        __syncthreads();
    }

    const int er = lane >> 2;
    const int ec = (lane & 3) * 2;
    float* Cb = Cout + (size_t)b * outBatchStride;
    const float* Rb = RES ? (Res + (size_t)b * CC * TT) : nullptr;
#pragma unroll
    for (int mi = 0; mi < 4; mi++) {
#pragma unroll
        for (int nj = 0; nj < 4; nj++) {
            const int m = m0 + wm + mi * 16 + er;
            const int n = n0 + wn + nj * 8 + ec;
            float2 v0 = make_float2(acc[mi][nj][0], acc[mi][nj][1]);
            float2 v1 = make_float2(acc[mi][nj][2], acc[mi][nj][3]);
            if (RES) {
                const float2 r0 = *(const float2*)(Rb + (size_t)m * TT + n);
                const float2 r1 = *(const float2*)(Rb + (size_t)(m + 8) * TT + n);
                v0.x += r0.x; v0.y += r0.y;
                v1.x += r1.x; v1.y += r1.y;
            }
            *(float2*)(Cb + (size_t)m * TT + n) = v0;
            *(float2*)(Cb + (size_t)(m + 8) * TT + n) = v1;
        }
    }
}

// ===========================================================================
// Tensor-core flash attention.
// CTA = (q-tile 128, h, b), 8 warps x 16 q rows, kt-tile 128, split bf16.
// Writes O directly into g_cT_hi/lo ([b][t][c]) for the projection GEMM.
// ===========================================================================
__device__ __forceinline__ void attn_load_stage(uint32_t st, int bh, int k0, int tid)
{
    const __nv_bfloat16* kh = g_kT_hi + ((size_t)bh * TT + k0) * DH;
    const __nv_bfloat16* kl = g_kT_lo + ((size_t)bh * TT + k0) * DH;
    for (int i = tid; i < 128 * 8; i += 256) {
        const int r = i >> 3, c = i & 7;
        const uint32_t d = st + (uint32_t)(r * QPITCH + c * 8) * 2;
        cp16(d, kh + (size_t)r * DH + c * 8);
        cp16(d + AQ_B, kl + (size_t)r * DH + c * 8);
    }
    const __nv_bfloat16* vh = g_v_hi + (size_t)bh * DH * TT + k0;
    const __nv_bfloat16* vl = g_v_lo + (size_t)bh * DH * TT + k0;
    for (int i = tid; i < 64 * 16; i += 256) {
        const int r = i >> 4, c = i & 15;
        const uint32_t d = st + 2 * AQ_B + (uint32_t)(r * VPITCH + c * 8) * 2;
        cp16(d, vh + (size_t)r * TT + c * 8);
        cp16(d + AV_B, vl + (size_t)r * TT + c * 8);
    }
}

__global__ void __launch_bounds__(256, 1) attn_mma()
{
    extern __shared__ char smem[];
    const uint32_t sb = smem_u32(smem);
    const uint32_t sQh = sb, sQl = sb + AQ_B;
    const uint32_t stage0 = sb + 2 * AQ_B;

    const int tid = threadIdx.x;
    const int wq = tid >> 5;
    const int lane = tid & 31;
    const int b = blockIdx.z, h = blockIdx.y;
    const int bh = b * HH + h;
    const int q0 = blockIdx.x * 128;

    // issue Q + K0/V0 loads in one group
    {
        const __nv_bfloat16* qh = g_qT_hi + ((size_t)bh * TT + q0) * DH;
        const __nv_bfloat16* ql = g_qT_lo + ((size_t)bh * TT + q0) * DH;
        for (int i = tid; i < 128 * 8; i += 256) {
            const int r = i >> 3, c = i & 7;
            const uint32_t d = sQh + (uint32_t)(r * QPITCH + c * 8) * 2;
            cp16(d, qh + (size_t)r * DH + c * 8);
            cp16(d + AQ_B, ql + (size_t)r * DH + c * 8);
        }
        attn_load_stage(stage0, bh, 0, tid);
        cp_commit();
    }

    const int a_row = lane & 15;
    const int a_ksel = (lane >> 4) * 8;
    const int b_row = lane & 7;
    const int b_ksel = ((lane >> 3) & 1) * 8;

    uint32_t qfh[4][4], qfl[4][4];
    float O[8][4];
    float m0 = -__int_as_float(0x7f800000), m1 = m0;
    float l0 = 0.0f, l1 = 0.0f;
#pragma unroll
    for (int d = 0; d < 8; d++)
#pragma unroll
        for (int r = 0; r < 4; r++) O[d][r] = 0.0f;

    for (int kt = 0; kt < TT / 128; kt++) {
        const uint32_t stb = stage0 + (uint32_t)(kt & 1) * ASTAGE_B;
        if (kt + 1 < TT / 128) {
            attn_load_stage(stage0 + (uint32_t)((kt + 1) & 1) * ASTAGE_B,
                            bh, (kt + 1) * 128, tid);
            cp_commit();
            asm volatile("cp.async.wait_group 1;\n" ::: "memory");
        } else {
            asm volatile("cp.async.wait_group 0;\n" ::: "memory");
        }
        __syncthreads();

        if (kt == 0) {
#pragma unroll
            for (int ks = 0; ks < 4; ks++) {
                const uint32_t off =
                    (uint32_t)((wq * 16 + a_row) * QPITCH + ks * 16 + a_ksel) * 2;
                ldmatrix_x4(qfh[ks][0], qfh[ks][1], qfh[ks][2], qfh[ks][3], sQh + off);
                ldmatrix_x4(qfl[ks][0], qfl[ks][1], qfl[ks][2], qfl[ks][3], sQl + off);
            }
        }

        // ---- S = Q K^T on this kt tile (16 q x 128 kt per warp) ----
        float S[16][4];
#pragma unroll
        for (int n = 0; n < 16; n++)
#pragma unroll
            for (int r = 0; r < 4; r++) S[n][r] = 0.0f;

        const uint32_t Kh = stb, Kl = stb + AQ_B;
#pragma unroll
        for (int n = 0; n < 16; n++) {
#pragma unroll
            for (int ks = 0; ks < 4; ks++) {
                const uint32_t off =
                    (uint32_t)((n * 8 + b_row) * QPITCH + ks * 16 + b_ksel) * 2;
                uint32_t kh0, kh1, kl0, kl1;
                ldmatrix_x2(kh0, kh1, Kh + off);
                ldmatrix_x2(kl0, kl1, Kl + off);
                mma_bf16(S[n], qfh[ks][0], qfh[ks][1], qfh[ks][2], qfh[ks][3], kh0, kh1);
                mma_bf16(S[n], qfh[ks][0], qfh[ks][1], qfh[ks][2], qfh[ks][3], kl0, kl1);
                mma_bf16(S[n], qfl[ks][0], qfl[ks][1], qfl[ks][2], qfl[ks][3], kh0, kh1);
            }
        }

        // ---- online softmax (rows r = lane/4 and r+8) ----
        float mx0 = -__int_as_float(0x7f800000), mx1 = mx0;
#pragma unroll
        for (int n = 0; n < 16; n++) {
            mx0 = fmaxf(mx0, fmaxf(S[n][0], S[n][1]));
            mx1 = fmaxf(mx1, fmaxf(S[n][2], S[n][3]));
        }
        mx0 = fmaxf(mx0, __shfl_xor_sync(0xffffffffu, mx0, 1));
        mx0 = fmaxf(mx0, __shfl_xor_sync(0xffffffffu, mx0, 2));
        mx1 = fmaxf(mx1, __shfl_xor_sync(0xffffffffu, mx1, 1));
        mx1 = fmaxf(mx1, __shfl_xor_sync(0xffffffffu, mx1, 2));
        const float mn0 = fmaxf(m0, mx0), mn1 = fmaxf(m1, mx1);
        const float al0 = __expf(m0 - mn0), al1 = __expf(m1 - mn1);
        float s0 = 0.0f, s1 = 0.0f;
#pragma unroll
        for (int n = 0; n < 16; n++) {
            S[n][0] = __expf(S[n][0] - mn0);
            S[n][1] = __expf(S[n][1] - mn0);
            S[n][2] = __expf(S[n][2] - mn1);
            S[n][3] = __expf(S[n][3] - mn1);
            s0 += S[n][0] + S[n][1];
            s1 += S[n][2] + S[n][3];
        }
        s0 += __shfl_xor_sync(0xffffffffu, s0, 1);
        s0 += __shfl_xor_sync(0xffffffffu, s0, 2);
        s1 += __shfl_xor_sync(0xffffffffu, s1, 1);
        s1 += __shfl_xor_sync(0xffffffffu, s1, 2);
        l0 = l0 * al0 + s0;
        l1 = l1 * al1 + s1;
        m0 = mn0;
        m1 = mn1;
#pragma unroll
        for (int d = 0; d < 8; d++) {
            O[d][0] *= al0; O[d][1] *= al0;
            O[d][2] *= al1; O[d][3] *= al1;
        }

        // ---- O += P V (repack S accum -> A frags, split hi/lo) ----
        const uint32_t Vh = stb + 2 * AQ_B, Vl = stb + 2 * AQ_B + AV_B;
#pragma unroll
        for (int u = 0; u < 8; u++) {
            uint32_t ph[4], pl[4];
            split2(S[2 * u][0], S[2 * u][1], ph[0], pl[0]);
            split2(S[2 * u][2], S[2 * u][3], ph[1], pl[1]);
            split2(S[2 * u + 1][0], S[2 * u + 1][1], ph[2], pl[2]);
            split2(S[2 * u + 1][2], S[2 * u + 1][3], ph[3], pl[3]);
#pragma unroll
            for (int dn = 0; dn < 8; dn++) {
                const uint32_t off =
                    (uint32_t)((dn * 8 + b_row) * VPITCH + u * 16 + b_ksel) * 2;
                uint32_t vh0, vh1, vl0, vl1;
                ldmatrix_x2(vh0, vh1, Vh + off);
                ldmatrix_x2(vl0, vl1, Vl + off);
                mma_bf16(O[dn], ph[0], ph[1], ph[2], ph[3], vh0, vh1);
                mma_bf16(O[dn], ph[0], ph[1], ph[2], ph[3], vl0, vl1);
                mma_bf16(O[dn], pl[0], pl[1], pl[2], pl[3], vh0, vh1);
            }
        }
        __syncthreads();
    }

    // ---- epilogue: O/l, split hi/lo, write to cT layout [b][t][c] ----
    const float r0 = 1.0f / l0, r1 = 1.0f / l1;
    const int row0 = q0 + wq * 16 + (lane >> 2);
    const size_t base0 = ((size_t)b * TT + row0) * CC + h * DH;
    const size_t base1 = base0 + (size_t)8 * CC;
#pragma unroll
    for (int dn = 0; dn < 8; dn++) {
        const int col = dn * 8 + 2 * (lane & 3);
        uint32_t hi, lo;
        split2(O[dn][0] * r0, O[dn][1] * r0, hi, lo);
        *(uint32_t*)&g_cT_hi[base0 + col] = hi;
        *(uint32_t*)&g_cT_lo[base0 + col] = lo;
        split2(O[dn][2] * r1, O[dn][3] * r1, hi, lo);
        *(uint32_t*)&g_cT_hi[base1 + col] = hi;
        *(uint32_t*)&g_cT_lo[base1 + col] = lo;
    }
}

// ===========================================================================
// LayerNorm (unchanged)
// ===========================================================================
__global__ void __launch_bounds__(256) ln_kernel(
    const float* __restrict__ gamma, const float* __restrict__ beta,
    float* __restrict__ out)
{
    const int tx = threadIdx.x, ty = threadIdx.y;
    const int b = blockIdx.y;
    const int t = blockIdx.x * 32 + tx;
    const float* yb = g_y + (long)b * CC * TT;

    float s = 0.0f, s2 = 0.0f;
    for (int c = ty; c < CC; c += 8) {
        const float v = yb[(long)c * TT + t];
        s += v;
        s2 += v * v;
    }
    __shared__ float rs[8][32], rq[8][32], mu_s[32], rstd_s[32];
    rs[ty][tx] = s;
    rq[ty][tx] = s2;
    __syncthreads();
    if (ty == 0) {
        float S = 0.0f, S2 = 0.0f;
#pragma unroll
        for (int k = 0; k < 8; k++) { S += rs[k][tx]; S2 += rq[k][tx]; }
        const float mu = S * (1.0f / CC);
        const float var = S2 * (1.0f / CC) - mu * mu;
        mu_s[tx] = mu;
        rstd_s[tx] = rsqrtf(var + LN_EPS);
    }
    __syncthreads();
    const float mu = mu_s[tx], rstd = rstd_s[tx];
    float* ob = out + (long)b * CC * TT;
    for (int c = ty; c < CC; c += 8) {
        const float v = yb[(long)c * TT + t];
        ob[(long)c * TT + t] = (v - mu) * rstd * gamma[c] + beta[c];
    }
}

// ===========================================================================
extern "C" void kernel_launch(void* const* d_in, const int* in_sizes, int n_in,
                              void* d_out, int out_size)
{
    const float* x     = (const float*)d_in[0];
    const float* wqkv  = (const float*)d_in[1];
    const float* wfc   = (const float*)d_in[2];
    const float* gamma = (const float*)d_in[3];
    const float* beta  = (const float*)d_in[4];
    float* out = (float*)d_out;

    float *qkv, *y;
    cudaGetSymbolAddress((void**)&qkv, g_qkv);
    cudaGetSymbolAddress((void**)&y, g_y);
    __nv_bfloat16 *wqh, *wql, *wfh, *wfl, *xth, *xtl, *cth, *ctl;
    cudaGetSymbolAddress((void**)&wqh, g_wqkv_hi);
    cudaGetSymbolAddress((void**)&wql, g_wqkv_lo);
    cudaGetSymbolAddress((void**)&wfh, g_wfc_hi);
    cudaGetSymbolAddress((void**)&wfl, g_wfc_lo);
    cudaGetSymbolAddress((void**)&xth, g_xT_hi);
    cudaGetSymbolAddress((void**)&xtl, g_xT_lo);
    cudaGetSymbolAddress((void**)&cth, g_cT_hi);
    cudaGetSymbolAddress((void**)&ctl, g_cT_lo);

    cudaFuncSetAttribute(hgemm<false>, cudaFuncAttributeMaxDynamicSharedMemorySize, GEMM_SMEM);
    cudaFuncSetAttribute(hgemm<true>, cudaFuncAttributeMaxDynamicSharedMemorySize, GEMM_SMEM);
    cudaFuncSetAttribute(attn_mma, cudaFuncAttributeMaxDynamicSharedMemorySize, ATTN_SMEM);

    // 0) precision-split conversions
    split_kernel<<<(3 * CC * CC + 255) / 256, 256>>>(wqkv, wqh, wql, 3 * CC * CC);
    split_kernel<<<(CC * CC + 255) / 256, 256>>>(wfc, wfh, wfl, CC * CC);
    tsplit_kernel<<<dim3(TT / 32, CC / 32, BB), dim3(32, 8)>>>(x, xth, xtl);

    // 1) QKV = w_qkv @ x
    hgemm<false><<<dim3(TT / GM_NT, 3 * CC / GM_MT, BB), 256, GEMM_SMEM>>>(
        wqh, wql, xth, xtl, nullptr, qkv, (long)3 * CC * TT);

    // 2) reshape/split QKV for attention
    qkv_split_kernel<<<dim3(TT / 32, DH / 32, BB * HH), dim3(32, 8)>>>();

    // 3) tensor-core flash attention -> g_cT hi/lo directly
    attn_mma<<<dim3(TT / 128, HH, BB), 256, ATTN_SMEM>>>();

    // 4) y = w_fc @ ctx + x (fused residual)
    hgemm<true><<<dim3(TT / GM_NT, CC / GM_MT, BB), 256, GEMM_SMEM>>>(
        wfh, wfl, cth, ctl, x, y, (long)CC * TT);

    // 5) LayerNorm -> out
    ln_kernel<<<dim3(TT / 32, BB), dim3(32, 8)>>>(gamma, beta, out);
}